// round 13
// baseline (speedup 1.0000x reference)
#include <cuda_runtime.h>
#include <cuda_bf16.h>
#include <math.h>

typedef unsigned long long ull;
typedef unsigned int u32;

#define SL 36
#define TL 20
#define SENT (1u << 19)
#define TENT (1u << 17)
#define SMASK (SENT - 1u)
#define TMASK (TENT - 1u)
#define HID 128
#define ENC 112
#define NSLOT (SL + TL)
#define P 32
#define MAXB 131072
#define VROW 132

__device__ __align__(16) u32 g_w1hi[4 * 8 * 32 * 8];
__device__ __align__(16) u32 g_w1lo[4 * 8 * 32 * 8];
__device__ __align__(16) u32 g_w2hi[4 * 8 * 32 * 8];
__device__ __align__(16) u32 g_w2lo[4 * 8 * 32 * 8];
__device__ float g_res[NSLOT];

// ---- fp32x2 helpers ---------------------------------------------------------
__device__ __forceinline__ ull splat2(float v) {
    ull r; asm("mov.b64 %0, {%1, %1};" : "=l"(r) : "f"(v)); return r;
}
__device__ __forceinline__ float2 unpack2(ull v) {
    float2 r; asm("mov.b64 {%0, %1}, %2;" : "=f"(r.x), "=f"(r.y) : "l"(v)); return r;
}
__device__ __forceinline__ ull fma2(ull a, ull b, ull c) {
    ull d; asm("fma.rn.f32x2 %0, %1, %2, %3;" : "=l"(d) : "l"(a), "l"(b), "l"(c)); return d;
}
__device__ __forceinline__ ull mul2(ull a, ull b) {
    ull d; asm("mul.rn.f32x2 %0, %1, %2;" : "=l"(d) : "l"(a), "l"(b)); return d;
}

// ---- bf16 split / mma helpers ------------------------------------------------
__device__ __forceinline__ void split2(float x0, float x1, u32& hp, u32& lp) {
    __nv_bfloat16 h0 = __float2bfloat16(x0);
    __nv_bfloat16 h1 = __float2bfloat16(x1);
    __nv_bfloat16 l0 = __float2bfloat16(x0 - __bfloat162float(h0));
    __nv_bfloat16 l1 = __float2bfloat16(x1 - __bfloat162float(h1));
    hp = ((u32)__bfloat16_as_ushort(h1) << 16) | __bfloat16_as_ushort(h0);
    lp = ((u32)__bfloat16_as_ushort(l1) << 16) | __bfloat16_as_ushort(l0);
}

__device__ __forceinline__ void mma16816(float* d, u32 a0, u32 a1, u32 a2, u32 a3,
                                         u32 b0, u32 b1) {
    asm volatile(
        "mma.sync.aligned.m16n8k16.row.col.f32.bf16.bf16.f32 "
        "{%0,%1,%2,%3}, {%4,%5,%6,%7}, {%8,%9}, {%0,%1,%2,%3};"
        : "+f"(d[0]), "+f"(d[1]), "+f"(d[2]), "+f"(d[3])
        : "r"(a0), "r"(a1), "r"(a2), "r"(a3), "r"(b0), "r"(b1));
}

__device__ __forceinline__ int bidx(int kt, int nt, int reg, int lane) {
    return ((kt * 4 + nt) * 2 + reg) * 32 + lane;
}

// ============================================================================
// setup kernel
// ============================================================================
__global__ void setup_kernel(const float* __restrict__ w1, const float* __restrict__ w2) {
    int t = blockIdx.x * blockDim.x + threadIdx.x;
    if (blockIdx.x == 0 && threadIdx.x < NSLOT) {
        int s = threadIdx.x;
        double bs = (s < SL) ? (double)1.38f : (double)1.5f;
        int e = (s < SL) ? s : s - SL;
        g_res[s] = floorf(16.0f * (float)pow(bs, (double)e));
    }
    int r     = t & 7;
    int lane  = (t >> 3) & 31;
    int kt    = (t >> 8) & 7;
    int w     = (t >> 11) & 3;
    int half  = (t >> 13) & 1;
    int layer = (t >> 14) & 1;
    int g  = lane >> 2;
    int tg = lane & 3;
    int mt = r >> 2;
    int rr = r & 3;
    int j  = w * 32 + mt * 16 + g + ((rr & 1) ? 8 : 0);
    int k0 = kt * 16 + tg * 2 + ((rr >> 1) ? 8 : 0);
    int k1 = k0 + 1;
    const float* W = layer ? w2 : w1;
    float x0 = (layer || k0 < ENC) ? W[k0 * HID + j] : 0.f;
    float x1 = (layer || k1 < ENC) ? W[k1 * HID + j] : 0.f;
    u32 hp, lp;
    split2(x0, x1, hp, lp);
    int idx = ((w * 8 + kt) * 32 + lane) * 8 + r;
    u32 val = half ? lp : hp;
    if (layer == 0) { if (half) g_w1lo[idx] = val; else g_w1hi[idx] = val; }
    else            { if (half) g_w2lo[idx] = val; else g_w2hi[idx] = val; }
}

// ============================================================================
// Fused kernel: encode (predicated paired gathers) -> bf16 fragments -> mma MLP
// ============================================================================
__global__ __launch_bounds__(128, 6)
void fused_kernel(const float4* __restrict__ coords,
                  const float2* __restrict__ stab,
                  const float2* __restrict__ ttab,
                  const float* __restrict__ b1, const float* __restrict__ g1,
                  const float* __restrict__ bt1,
                  const float* __restrict__ b2, const float* __restrict__ g2,
                  const float* __restrict__ bt2,
                  const float* __restrict__ w3, const float* __restrict__ b3,
                  float* __restrict__ out, int B)
{
    __shared__ __align__(16) unsigned char smraw[32 * VROW * 4];
    u32* bhi = (u32*)smraw;
    u32* blo = bhi + 2048;
    float* vmat = (float*)smraw;

    const int tid  = threadIdx.x;
    const int w    = tid >> 5;
    const int lane = tid & 31;
    const int base = blockIdx.x * P;

    bhi[1792 + tid] = 0u; bhi[1920 + tid] = 0u;
    blo[1792 + tid] = 0u; blo[1920 + tid] = 0u;

    int pi = base + lane;
    if (pi >= B) pi = B - 1;
    const float4 c = __ldg(&coords[pi]);

#pragma unroll 1
    for (int i = 0; i < 14; i++) {
        int s = w + 4 * i;
        float2 a;
        if (s < SL) {
            float r = __ldg(&g_res[s]);
            float x = c.x * r, y = c.y * r, z = c.z * r;
            float fx = floorf(x), fy = floorf(y), fz = floorf(z);
            float wx = x - fx, wy = y - fy, wz = z - fz;
            float mx = 1.f - wx, my = 1.f - wy, mz = 1.f - wz;
            unsigned ux = (unsigned)fx, uy = (unsigned)fy, uz = (unsigned)fz;
            unsigned hy0 = uy * 2654435761u, hy1 = (uy + 1u) * 2654435761u;
            unsigned hz0 = uz * 805459861u,  hz1 = (uz + 1u) * 805459861u;
            float cw0 = my * mz, cw1 = wy * mz, cw2 = my * wz, cw3 = wy * wz;
            const float2* tb = stab + (size_t)s * SENT;
            const bool uxodd = (ux & 1u) != 0u;
            const unsigned ux1 = ux + 1u;
            ull acc = 0ull;
            // For each (by,bz) pair: one aligned LDG.128 always; if ux is even
            // it contains BOTH x-corners (h1 = h0^1). Odd lanes fix up the
            // second corner with a predicated LDG.64 (no branch divergence).
#pragma unroll
            for (int pr = 0; pr < 4; pr++) {
                unsigned m = (pr & 1 ? hy1 : hy0) ^ (pr & 2 ? hz1 : hz0);
                float cw = (pr == 0) ? cw0 : (pr == 1) ? cw1 : (pr == 2) ? cw2 : cw3;
                unsigned h0 = (ux ^ m) & SMASK;
                ulonglong2 q = __ldg((const ulonglong2*)(tb + (h0 & ~1u)));
                ull cA = (h0 & 1u) ? q.y : q.x;
                ull cB = (h0 & 1u) ? q.x : q.y;
                if (uxodd) cB = *(const ull*)(tb + ((ux1 ^ m) & SMASK));
                acc = fma2(cA, splat2(mx * cw), acc);
                acc = fma2(cB, splat2(wx * cw), acc);
            }
            a = unpack2(acc);
        } else {
            int l = s - SL;
            float r  = __ldg(&g_res[s]);
            float tx = c.w * r;
            float tf = floorf(tx);
            float tw = tx - tf;
            unsigned t0 = (unsigned)tf;
            const float2* tb = ttab + (size_t)l * TENT;
            unsigned i0 = t0 & TMASK;
            ulonglong2 q = __ldg((const ulonglong2*)(tb + (i0 & ~1u)));
            ull f0 = (i0 & 1u) ? q.y : q.x;
            ull f1 = (i0 & 1u) ? q.x : q.y;
            if (i0 & 1u) f1 = *(const ull*)(tb + ((i0 + 1u) & TMASK));
            ull acc = mul2(f0, splat2(1.f - tw));
            acc = fma2(f1, splat2(tw), acc);
            a = unpack2(acc);
        }
        u32 hp, lp;
        split2(a.x, a.y, hp, lp);
        int kt = s >> 3, qq = s & 7, reg = qq >> 2, tgq = qq & 3;
        int idx = bidx(kt, lane >> 3, reg, (lane & 7) * 4 + tgq);
        bhi[idx] = hp;
        blo[idx] = lp;
    }
    __syncthreads();

#pragma unroll 1
    for (int layer = 0; layer < 2; layer++) {
        const u32* WH = layer ? g_w2hi : g_w1hi;
        const u32* WL = layer ? g_w2lo : g_w1lo;

        float d[2][4][4];
#pragma unroll
        for (int mt = 0; mt < 2; mt++)
#pragma unroll
            for (int nt = 0; nt < 4; nt++)
#pragma unroll
                for (int e = 0; e < 4; e++) d[mt][nt][e] = 0.f;

#pragma unroll
        for (int kt = 0; kt < 8; kt++) {
            const uint4* pa = (const uint4*)(WH + (size_t)(((w * 8 + kt) * 32 + lane) * 8));
            uint4 A0 = __ldg(pa);
            uint4 A1 = __ldg(pa + 1);
            u32 bh[4][2], bl[4][2];
#pragma unroll
            for (int nt = 0; nt < 4; nt++) {
                bh[nt][0] = bhi[bidx(kt, nt, 0, lane)];
                bh[nt][1] = bhi[bidx(kt, nt, 1, lane)];
                bl[nt][0] = blo[bidx(kt, nt, 0, lane)];
                bl[nt][1] = blo[bidx(kt, nt, 1, lane)];
            }
#pragma unroll
            for (int nt = 0; nt < 4; nt++) {
                mma16816(d[0][nt], A0.x, A0.y, A0.z, A0.w, bh[nt][0], bh[nt][1]);
                mma16816(d[1][nt], A1.x, A1.y, A1.z, A1.w, bh[nt][0], bh[nt][1]);
                mma16816(d[0][nt], A0.x, A0.y, A0.z, A0.w, bl[nt][0], bl[nt][1]);
                mma16816(d[1][nt], A1.x, A1.y, A1.z, A1.w, bl[nt][0], bl[nt][1]);
            }
            const uint4* pl = (const uint4*)(WL + (size_t)(((w * 8 + kt) * 32 + lane) * 8));
            uint4 L0 = __ldg(pl);
            uint4 L1 = __ldg(pl + 1);
#pragma unroll
            for (int nt = 0; nt < 4; nt++) {
                mma16816(d[0][nt], L0.x, L0.y, L0.z, L0.w, bh[nt][0], bh[nt][1]);
                mma16816(d[1][nt], L1.x, L1.y, L1.z, L1.w, bh[nt][0], bh[nt][1]);
            }
        }
        __syncthreads();

        const int g  = lane >> 2;
        const int tg = lane & 3;
        const float* bias = layer ? b2 : b1;
#pragma unroll
        for (int mt = 0; mt < 2; mt++) {
            int j0 = w * 32 + mt * 16 + g;
            float bA = __ldg(bias + j0);
            float bB = __ldg(bias + j0 + 8);
#pragma unroll
            for (int nt = 0; nt < 4; nt++) {
                int p0 = nt * 8 + tg * 2;
                vmat[p0 * VROW + j0]           = fmaxf(d[mt][nt][0] + bA, 0.f);
                vmat[(p0 + 1) * VROW + j0]     = fmaxf(d[mt][nt][1] + bA, 0.f);
                vmat[p0 * VROW + j0 + 8]       = fmaxf(d[mt][nt][2] + bB, 0.f);
                vmat[(p0 + 1) * VROW + j0 + 8] = fmaxf(d[mt][nt][3] + bB, 0.f);
            }
        }
        __syncthreads();

        const int p  = tid >> 2;
        const int q4 = tid & 3;
        float v[32];
        float s1 = 0.f, s2 = 0.f;
        const float4* row = (const float4*)(vmat + p * VROW + q4 * 32);
#pragma unroll
        for (int i8 = 0; i8 < 8; i8++) {
            float4 t = row[i8];
            v[4 * i8] = t.x; v[4 * i8 + 1] = t.y; v[4 * i8 + 2] = t.z; v[4 * i8 + 3] = t.w;
            s1 += (t.x + t.y) + (t.z + t.w);
            s2 += (t.x * t.x + t.y * t.y) + (t.z * t.z + t.w * t.w);
        }
        s1 += __shfl_xor_sync(0xffffffffu, s1, 1);
        s1 += __shfl_xor_sync(0xffffffffu, s1, 2);
        s2 += __shfl_xor_sync(0xffffffffu, s2, 1);
        s2 += __shfl_xor_sync(0xffffffffu, s2, 2);
        float m   = s1 * (1.f / HID);
        float var = s2 * (1.f / HID) - m * m;
        float rs  = rsqrtf(var + 1e-5f);

        const float* gg = (layer ? g2 : g1) + q4 * 32;
        const float* bb = (layer ? bt2 : bt1) + q4 * 32;

        if (layer == 0) {
            __syncthreads();
#pragma unroll
            for (int mm = 0; mm < 16; mm++) {
                float x0 = (v[2 * mm]     - m) * rs * __ldg(gg + 2 * mm)     + __ldg(bb + 2 * mm);
                float x1 = (v[2 * mm + 1] - m) * rs * __ldg(gg + 2 * mm + 1) + __ldg(bb + 2 * mm + 1);
                int kp = q4 * 16 + mm;
                int kt = kp >> 3, qq = kp & 7, reg = qq >> 2, tgq = qq & 3;
                u32 hp, lp;
                split2(x0, x1, hp, lp);
                int idx = bidx(kt, p >> 3, reg, (p & 7) * 4 + tgq);
                bhi[idx] = hp;
                blo[idx] = lp;
            }
            __syncthreads();
        } else {
            float part = 0.f;
#pragma unroll
            for (int i = 0; i < 32; i++) {
                float x = (v[i] - m) * rs * __ldg(gg + i) + __ldg(bb + i);
                part = fmaf(x, __ldg(w3 + q4 * 32 + i), part);
            }
            part += __shfl_xor_sync(0xffffffffu, part, 1);
            part += __shfl_xor_sync(0xffffffffu, part, 2);
            if (q4 == 0) {
                int po = base + p;
                if (po < B) out[po] = part + __ldg(b3);
            }
        }
    }
}

extern "C" void kernel_launch(void* const* d_in, const int* in_sizes, int n_in,
                              void* d_out, int out_size) {
    const float4* coords = (const float4*)d_in[0];
    const float2* stab   = (const float2*)d_in[1];
    const float2* ttab   = (const float2*)d_in[2];
    const float*  w1     = (const float*)d_in[3];
    const float*  b1     = (const float*)d_in[4];
    const float*  g1     = (const float*)d_in[5];
    const float*  be1    = (const float*)d_in[6];
    const float*  w2     = (const float*)d_in[7];
    const float*  b2     = (const float*)d_in[8];
    const float*  g2     = (const float*)d_in[9];
    const float*  be2    = (const float*)d_in[10];
    const float*  w3     = (const float*)d_in[11];
    const float*  b3     = (const float*)d_in[12];
    float* out = (float*)d_out;

    int B = in_sizes[0] / 4;
    if (B > MAXB) B = MAXB;
    int blocks = (B + P - 1) / P;

    setup_kernel<<<128, 256>>>(w1, w2);
    fused_kernel<<<blocks, 128>>>(coords, stab, ttab,
                                  b1, g1, be1, b2, g2, be2, w3, b3, out, B);
}

// round 14
// speedup vs baseline: 1.0057x; 1.0057x over previous
#include <cuda_runtime.h>
#include <cuda_bf16.h>
#include <math.h>

typedef unsigned long long ull;
typedef unsigned int u32;

#define SL 36
#define TL 20
#define SENT (1u << 19)
#define TENT (1u << 17)
#define SMASK (SENT - 1u)
#define TMASK (TENT - 1u)
#define HID 128
#define ENC 112
#define NSLOT (SL + TL)
#define P 32
#define MAXB 131072
#define VROW 132

__device__ __align__(16) u32 g_w1hi[4 * 8 * 32 * 8];
__device__ __align__(16) u32 g_w1lo[4 * 8 * 32 * 8];
__device__ __align__(16) u32 g_w2hi[4 * 8 * 32 * 8];
__device__ __align__(16) u32 g_w2lo[4 * 8 * 32 * 8];
__device__ float g_res[NSLOT];

// ---- fp32x2 helpers ---------------------------------------------------------
__device__ __forceinline__ ull splat2(float v) {
    ull r; asm("mov.b64 %0, {%1, %1};" : "=l"(r) : "f"(v)); return r;
}
__device__ __forceinline__ float2 unpack2(ull v) {
    float2 r; asm("mov.b64 {%0, %1}, %2;" : "=f"(r.x), "=f"(r.y) : "l"(v)); return r;
}
__device__ __forceinline__ ull fma2(ull a, ull b, ull c) {
    ull d; asm("fma.rn.f32x2 %0, %1, %2, %3;" : "=l"(d) : "l"(a), "l"(b), "l"(c)); return d;
}
__device__ __forceinline__ ull mul2(ull a, ull b) {
    ull d; asm("mul.rn.f32x2 %0, %1, %2;" : "=l"(d) : "l"(a), "l"(b)); return d;
}

// ---- bf16 split / mma helpers ------------------------------------------------
__device__ __forceinline__ void split2(float x0, float x1, u32& hp, u32& lp) {
    __nv_bfloat16 h0 = __float2bfloat16(x0);
    __nv_bfloat16 h1 = __float2bfloat16(x1);
    __nv_bfloat16 l0 = __float2bfloat16(x0 - __bfloat162float(h0));
    __nv_bfloat16 l1 = __float2bfloat16(x1 - __bfloat162float(h1));
    hp = ((u32)__bfloat16_as_ushort(h1) << 16) | __bfloat16_as_ushort(h0);
    lp = ((u32)__bfloat16_as_ushort(l1) << 16) | __bfloat16_as_ushort(l0);
}

__device__ __forceinline__ void mma16816(float* d, u32 a0, u32 a1, u32 a2, u32 a3,
                                         u32 b0, u32 b1) {
    asm volatile(
        "mma.sync.aligned.m16n8k16.row.col.f32.bf16.bf16.f32 "
        "{%0,%1,%2,%3}, {%4,%5,%6,%7}, {%8,%9}, {%0,%1,%2,%3};"
        : "+f"(d[0]), "+f"(d[1]), "+f"(d[2]), "+f"(d[3])
        : "r"(a0), "r"(a1), "r"(a2), "r"(a3), "r"(b0), "r"(b1));
}

__device__ __forceinline__ int bidx(int kt, int nt, int reg, int lane) {
    return ((kt * 4 + nt) * 2 + reg) * 32 + lane;
}

// ============================================================================
// setup kernel
// ============================================================================
__global__ void setup_kernel(const float* __restrict__ w1, const float* __restrict__ w2) {
    int t = blockIdx.x * blockDim.x + threadIdx.x;
    if (blockIdx.x == 0 && threadIdx.x < NSLOT) {
        int s = threadIdx.x;
        double bs = (s < SL) ? (double)1.38f : (double)1.5f;
        int e = (s < SL) ? s : s - SL;
        g_res[s] = floorf(16.0f * (float)pow(bs, (double)e));
    }
    int r     = t & 7;
    int lane  = (t >> 3) & 31;
    int kt    = (t >> 8) & 7;
    int w     = (t >> 11) & 3;
    int half  = (t >> 13) & 1;
    int layer = (t >> 14) & 1;
    int g  = lane >> 2;
    int tg = lane & 3;
    int mt = r >> 2;
    int rr = r & 3;
    int j  = w * 32 + mt * 16 + g + ((rr & 1) ? 8 : 0);
    int k0 = kt * 16 + tg * 2 + ((rr >> 1) ? 8 : 0);
    int k1 = k0 + 1;
    const float* W = layer ? w2 : w1;
    float x0 = (layer || k0 < ENC) ? W[k0 * HID + j] : 0.f;
    float x1 = (layer || k1 < ENC) ? W[k1 * HID + j] : 0.f;
    u32 hp, lp;
    split2(x0, x1, hp, lp);
    int idx = ((w * 8 + kt) * 32 + lane) * 8 + r;
    u32 val = half ? lp : hp;
    if (layer == 0) { if (half) g_w1lo[idx] = val; else g_w1hi[idx] = val; }
    else            { if (half) g_w2lo[idx] = val; else g_w2hi[idx] = val; }
}

// ============================================================================
// Fused kernel: encode (predicated paired gathers) -> bf16 fragments -> mma MLP
// ============================================================================
__global__ __launch_bounds__(128, 6)
void fused_kernel(const float4* __restrict__ coords,
                  const float2* __restrict__ stab,
                  const float2* __restrict__ ttab,
                  const float* __restrict__ b1, const float* __restrict__ g1,
                  const float* __restrict__ bt1,
                  const float* __restrict__ b2, const float* __restrict__ g2,
                  const float* __restrict__ bt2,
                  const float* __restrict__ w3, const float* __restrict__ b3,
                  float* __restrict__ out, int B)
{
    __shared__ __align__(16) unsigned char smraw[32 * VROW * 4];
    u32* bhi = (u32*)smraw;
    u32* blo = bhi + 2048;
    float* vmat = (float*)smraw;

    const int tid  = threadIdx.x;
    const int w    = tid >> 5;
    const int lane = tid & 31;
    const int base = blockIdx.x * P;

    bhi[1792 + tid] = 0u; bhi[1920 + tid] = 0u;
    blo[1792 + tid] = 0u; blo[1920 + tid] = 0u;

    int pi = base + lane;
    if (pi >= B) pi = B - 1;
    const float4 c = __ldg(&coords[pi]);

#pragma unroll 1
    for (int i = 0; i < 14; i++) {
        int s = w + 4 * i;
        float2 a;
        if (s < SL) {
            float r = __ldg(&g_res[s]);
            float x = c.x * r, y = c.y * r, z = c.z * r;
            float fx = floorf(x), fy = floorf(y), fz = floorf(z);
            float wx = x - fx, wy = y - fy, wz = z - fz;
            float mx = 1.f - wx, my = 1.f - wy, mz = 1.f - wz;
            unsigned ux = (unsigned)fx, uy = (unsigned)fy, uz = (unsigned)fz;
            unsigned hy0 = uy * 2654435761u, hy1 = (uy + 1u) * 2654435761u;
            unsigned hz0 = uz * 805459861u,  hz1 = (uz + 1u) * 805459861u;
            float cw0 = my * mz, cw1 = wy * mz, cw2 = my * wz, cw3 = wy * wz;
            const float2* tb = stab + (size_t)s * SENT;
            const bool uxodd = (ux & 1u) != 0u;
            const unsigned ux1 = ux + 1u;
            ull acc = 0ull;
            // For each (by,bz) pair: one aligned LDG.128 always; if ux is even
            // it contains BOTH x-corners (h1 = h0^1). Odd lanes fix up the
            // second corner with a predicated LDG.64 (no branch divergence).
#pragma unroll
            for (int pr = 0; pr < 4; pr++) {
                unsigned m = (pr & 1 ? hy1 : hy0) ^ (pr & 2 ? hz1 : hz0);
                float cw = (pr == 0) ? cw0 : (pr == 1) ? cw1 : (pr == 2) ? cw2 : cw3;
                unsigned h0 = (ux ^ m) & SMASK;
                ulonglong2 q = __ldg((const ulonglong2*)(tb + (h0 & ~1u)));
                ull cA = (h0 & 1u) ? q.y : q.x;
                ull cB = (h0 & 1u) ? q.x : q.y;
                if (uxodd) cB = *(const ull*)(tb + ((ux1 ^ m) & SMASK));
                acc = fma2(cA, splat2(mx * cw), acc);
                acc = fma2(cB, splat2(wx * cw), acc);
            }
            a = unpack2(acc);
        } else {
            int l = s - SL;
            float r  = __ldg(&g_res[s]);
            float tx = c.w * r;
            float tf = floorf(tx);
            float tw = tx - tf;
            unsigned t0 = (unsigned)tf;
            const float2* tb = ttab + (size_t)l * TENT;
            unsigned i0 = t0 & TMASK;
            ulonglong2 q = __ldg((const ulonglong2*)(tb + (i0 & ~1u)));
            ull f0 = (i0 & 1u) ? q.y : q.x;
            ull f1 = (i0 & 1u) ? q.x : q.y;
            if (i0 & 1u) f1 = *(const ull*)(tb + ((i0 + 1u) & TMASK));
            ull acc = mul2(f0, splat2(1.f - tw));
            acc = fma2(f1, splat2(tw), acc);
            a = unpack2(acc);
        }
        u32 hp, lp;
        split2(a.x, a.y, hp, lp);
        int kt = s >> 3, qq = s & 7, reg = qq >> 2, tgq = qq & 3;
        int idx = bidx(kt, lane >> 3, reg, (lane & 7) * 4 + tgq);
        bhi[idx] = hp;
        blo[idx] = lp;
    }
    __syncthreads();

#pragma unroll 1
    for (int layer = 0; layer < 2; layer++) {
        const u32* WH = layer ? g_w2hi : g_w1hi;
        const u32* WL = layer ? g_w2lo : g_w1lo;

        float d[2][4][4];
#pragma unroll
        for (int mt = 0; mt < 2; mt++)
#pragma unroll
            for (int nt = 0; nt < 4; nt++)
#pragma unroll
                for (int e = 0; e < 4; e++) d[mt][nt][e] = 0.f;

#pragma unroll
        for (int kt = 0; kt < 8; kt++) {
            const uint4* pa = (const uint4*)(WH + (size_t)(((w * 8 + kt) * 32 + lane) * 8));
            uint4 A0 = __ldg(pa);
            uint4 A1 = __ldg(pa + 1);
            u32 bh[4][2], bl[4][2];
#pragma unroll
            for (int nt = 0; nt < 4; nt++) {
                bh[nt][0] = bhi[bidx(kt, nt, 0, lane)];
                bh[nt][1] = bhi[bidx(kt, nt, 1, lane)];
                bl[nt][0] = blo[bidx(kt, nt, 0, lane)];
                bl[nt][1] = blo[bidx(kt, nt, 1, lane)];
            }
#pragma unroll
            for (int nt = 0; nt < 4; nt++) {
                mma16816(d[0][nt], A0.x, A0.y, A0.z, A0.w, bh[nt][0], bh[nt][1]);
                mma16816(d[1][nt], A1.x, A1.y, A1.z, A1.w, bh[nt][0], bh[nt][1]);
                mma16816(d[0][nt], A0.x, A0.y, A0.z, A0.w, bl[nt][0], bl[nt][1]);
                mma16816(d[1][nt], A1.x, A1.y, A1.z, A1.w, bl[nt][0], bl[nt][1]);
            }
            const uint4* pl = (const uint4*)(WL + (size_t)(((w * 8 + kt) * 32 + lane) * 8));
            uint4 L0 = __ldg(pl);
            uint4 L1 = __ldg(pl + 1);
#pragma unroll
            for (int nt = 0; nt < 4; nt++) {
                mma16816(d[0][nt], L0.x, L0.y, L0.z, L0.w, bh[nt][0], bh[nt][1]);
                mma16816(d[1][nt], L1.x, L1.y, L1.z, L1.w, bh[nt][0], bh[nt][1]);
            }
        }
        __syncthreads();

        const int g  = lane >> 2;
        const int tg = lane & 3;
        const float* bias = layer ? b2 : b1;
#pragma unroll
        for (int mt = 0; mt < 2; mt++) {
            int j0 = w * 32 + mt * 16 + g;
            float bA = __ldg(bias + j0);
            float bB = __ldg(bias + j0 + 8);
#pragma unroll
            for (int nt = 0; nt < 4; nt++) {
                int p0 = nt * 8 + tg * 2;
                vmat[p0 * VROW + j0]           = fmaxf(d[mt][nt][0] + bA, 0.f);
                vmat[(p0 + 1) * VROW + j0]     = fmaxf(d[mt][nt][1] + bA, 0.f);
                vmat[p0 * VROW + j0 + 8]       = fmaxf(d[mt][nt][2] + bB, 0.f);
                vmat[(p0 + 1) * VROW + j0 + 8] = fmaxf(d[mt][nt][3] + bB, 0.f);
            }
        }
        __syncthreads();

        const int p  = tid >> 2;
        const int q4 = tid & 3;
        float v[32];
        float s1 = 0.f, s2 = 0.f;
        const float4* row = (const float4*)(vmat + p * VROW + q4 * 32);
#pragma unroll
        for (int i8 = 0; i8 < 8; i8++) {
            float4 t = row[i8];
            v[4 * i8] = t.x; v[4 * i8 + 1] = t.y; v[4 * i8 + 2] = t.z; v[4 * i8 + 3] = t.w;
            s1 += (t.x + t.y) + (t.z + t.w);
            s2 += (t.x * t.x + t.y * t.y) + (t.z * t.z + t.w * t.w);
        }
        s1 += __shfl_xor_sync(0xffffffffu, s1, 1);
        s1 += __shfl_xor_sync(0xffffffffu, s1, 2);
        s2 += __shfl_xor_sync(0xffffffffu, s2, 1);
        s2 += __shfl_xor_sync(0xffffffffu, s2, 2);
        float m   = s1 * (1.f / HID);
        float var = s2 * (1.f / HID) - m * m;
        float rs  = rsqrtf(var + 1e-5f);

        const float* gg = (layer ? g2 : g1) + q4 * 32;
        const float* bb = (layer ? bt2 : bt1) + q4 * 32;

        if (layer == 0) {
            __syncthreads();
#pragma unroll
            for (int mm = 0; mm < 16; mm++) {
                float x0 = (v[2 * mm]     - m) * rs * __ldg(gg + 2 * mm)     + __ldg(bb + 2 * mm);
                float x1 = (v[2 * mm + 1] - m) * rs * __ldg(gg + 2 * mm + 1) + __ldg(bb + 2 * mm + 1);
                int kp = q4 * 16 + mm;
                int kt = kp >> 3, qq = kp & 7, reg = qq >> 2, tgq = qq & 3;
                u32 hp, lp;
                split2(x0, x1, hp, lp);
                int idx = bidx(kt, p >> 3, reg, (p & 7) * 4 + tgq);
                bhi[idx] = hp;
                blo[idx] = lp;
            }
            __syncthreads();
        } else {
            float part = 0.f;
#pragma unroll
            for (int i = 0; i < 32; i++) {
                float x = (v[i] - m) * rs * __ldg(gg + i) + __ldg(bb + i);
                part = fmaf(x, __ldg(w3 + q4 * 32 + i), part);
            }
            part += __shfl_xor_sync(0xffffffffu, part, 1);
            part += __shfl_xor_sync(0xffffffffu, part, 2);
            if (q4 == 0) {
                int po = base + p;
                if (po < B) out[po] = part + __ldg(b3);
            }
        }
    }
}

extern "C" void kernel_launch(void* const* d_in, const int* in_sizes, int n_in,
                              void* d_out, int out_size) {
    const float4* coords = (const float4*)d_in[0];
    const float2* stab   = (const float2*)d_in[1];
    const float2* ttab   = (const float2*)d_in[2];
    const float*  w1     = (const float*)d_in[3];
    const float*  b1     = (const float*)d_in[4];
    const float*  g1     = (const float*)d_in[5];
    const float*  be1    = (const float*)d_in[6];
    const float*  w2     = (const float*)d_in[7];
    const float*  b2     = (const float*)d_in[8];
    const float*  g2     = (const float*)d_in[9];
    const float*  be2    = (const float*)d_in[10];
    const float*  w3     = (const float*)d_in[11];
    const float*  b3     = (const float*)d_in[12];
    float* out = (float*)d_out;

    int B = in_sizes[0] / 4;
    if (B > MAXB) B = MAXB;
    int blocks = (B + P - 1) / P;

    setup_kernel<<<128, 256>>>(w1, w2);
    fused_kernel<<<blocks, 128>>>(coords, stab, ttab,
                                  b1, g1, be1, b2, g2, be2, w3, b3, out, B);
}

// round 15
// speedup vs baseline: 1.1194x; 1.1131x over previous
#include <cuda_runtime.h>
#include <cuda_bf16.h>
#include <math.h>

typedef unsigned long long ull;
typedef unsigned int u32;

#define SL 36
#define TL 20
#define SENT (1u << 19)
#define TENT (1u << 17)
#define SMASK (SENT - 1u)
#define TMASK (TENT - 1u)
#define HID 128
#define ENC 112
#define NSLOT (SL + TL)
#define P 32
#define MAXB 131072
#define VROW 132

__device__ __align__(16) u32 g_w1hi[4 * 8 * 32 * 8];
__device__ __align__(16) u32 g_w1lo[4 * 8 * 32 * 8];
__device__ __align__(16) u32 g_w2hi[4 * 8 * 32 * 8];
__device__ __align__(16) u32 g_w2lo[4 * 8 * 32 * 8];
__device__ float g_res[NSLOT];

// ---- fp32x2 helpers ---------------------------------------------------------
__device__ __forceinline__ ull splat2(float v) {
    ull r; asm("mov.b64 %0, {%1, %1};" : "=l"(r) : "f"(v)); return r;
}
__device__ __forceinline__ float2 unpack2(ull v) {
    float2 r; asm("mov.b64 {%0, %1}, %2;" : "=f"(r.x), "=f"(r.y) : "l"(v)); return r;
}
__device__ __forceinline__ ull fma2(ull a, ull b, ull c) {
    ull d; asm("fma.rn.f32x2 %0, %1, %2, %3;" : "=l"(d) : "l"(a), "l"(b), "l"(c)); return d;
}
__device__ __forceinline__ ull mul2(ull a, ull b) {
    ull d; asm("mul.rn.f32x2 %0, %1, %2;" : "=l"(d) : "l"(a), "l"(b)); return d;
}

// ---- bf16 split / mma helpers ------------------------------------------------
__device__ __forceinline__ void split2(float x0, float x1, u32& hp, u32& lp) {
    __nv_bfloat16 h0 = __float2bfloat16(x0);
    __nv_bfloat16 h1 = __float2bfloat16(x1);
    __nv_bfloat16 l0 = __float2bfloat16(x0 - __bfloat162float(h0));
    __nv_bfloat16 l1 = __float2bfloat16(x1 - __bfloat162float(h1));
    hp = ((u32)__bfloat16_as_ushort(h1) << 16) | __bfloat16_as_ushort(h0);
    lp = ((u32)__bfloat16_as_ushort(l1) << 16) | __bfloat16_as_ushort(l0);
}

__device__ __forceinline__ void mma16816(float* d, u32 a0, u32 a1, u32 a2, u32 a3,
                                         u32 b0, u32 b1) {
    asm volatile(
        "mma.sync.aligned.m16n8k16.row.col.f32.bf16.bf16.f32 "
        "{%0,%1,%2,%3}, {%4,%5,%6,%7}, {%8,%9}, {%0,%1,%2,%3};"
        : "+f"(d[0]), "+f"(d[1]), "+f"(d[2]), "+f"(d[3])
        : "r"(a0), "r"(a1), "r"(a2), "r"(a3), "r"(b0), "r"(b1));
}

__device__ __forceinline__ int bidx(int kt, int nt, int reg, int lane) {
    return ((kt * 4 + nt) * 2 + reg) * 32 + lane;
}

// ============================================================================
// setup kernel
// ============================================================================
__global__ void setup_kernel(const float* __restrict__ w1, const float* __restrict__ w2) {
    int t = blockIdx.x * blockDim.x + threadIdx.x;
    if (blockIdx.x == 0 && threadIdx.x < NSLOT) {
        int s = threadIdx.x;
        double bs = (s < SL) ? (double)1.38f : (double)1.5f;
        int e = (s < SL) ? s : s - SL;
        g_res[s] = floorf(16.0f * (float)pow(bs, (double)e));
    }
    int r     = t & 7;
    int lane  = (t >> 3) & 31;
    int kt    = (t >> 8) & 7;
    int w     = (t >> 11) & 3;
    int half  = (t >> 13) & 1;
    int layer = (t >> 14) & 1;
    int g  = lane >> 2;
    int tg = lane & 3;
    int mt = r >> 2;
    int rr = r & 3;
    int j  = w * 32 + mt * 16 + g + ((rr & 1) ? 8 : 0);
    int k0 = kt * 16 + tg * 2 + ((rr >> 1) ? 8 : 0);
    int k1 = k0 + 1;
    const float* W = layer ? w2 : w1;
    float x0 = (layer || k0 < ENC) ? W[k0 * HID + j] : 0.f;
    float x1 = (layer || k1 < ENC) ? W[k1 * HID + j] : 0.f;
    u32 hp, lp;
    split2(x0, x1, hp, lp);
    int idx = ((w * 8 + kt) * 32 + lane) * 8 + r;
    u32 val = half ? lp : hp;
    if (layer == 0) { if (half) g_w1lo[idx] = val; else g_w1hi[idx] = val; }
    else            { if (half) g_w2lo[idx] = val; else g_w2hi[idx] = val; }
}

// ============================================================================
// Fused kernel: encode -> bf16 fragments -> 3-term bf16 mma MLP.
// Encode loop unrolled x2 so ~16 gathers are in flight per warp.
// ============================================================================
__global__ __launch_bounds__(128, 6)
void fused_kernel(const float4* __restrict__ coords,
                  const float2* __restrict__ stab,
                  const float2* __restrict__ ttab,
                  const float* __restrict__ b1, const float* __restrict__ g1,
                  const float* __restrict__ bt1,
                  const float* __restrict__ b2, const float* __restrict__ g2,
                  const float* __restrict__ bt2,
                  const float* __restrict__ w3, const float* __restrict__ b3,
                  float* __restrict__ out, int B)
{
    __shared__ __align__(16) unsigned char smraw[32 * VROW * 4];
    u32* bhi = (u32*)smraw;
    u32* blo = bhi + 2048;
    float* vmat = (float*)smraw;

    const int tid  = threadIdx.x;
    const int w    = tid >> 5;
    const int lane = tid & 31;
    const int base = blockIdx.x * P;

    bhi[1792 + tid] = 0u; bhi[1920 + tid] = 0u;
    blo[1792 + tid] = 0u; blo[1920 + tid] = 0u;

    int pi = base + lane;
    if (pi >= B) pi = B - 1;
    const float4 c = __ldg(&coords[pi]);

#pragma unroll 2
    for (int i = 0; i < 14; i++) {
        int s = w + 4 * i;
        float2 a;
        if (s < SL) {
            float r = __ldg(&g_res[s]);
            float x = c.x * r, y = c.y * r, z = c.z * r;
            float fx = floorf(x), fy = floorf(y), fz = floorf(z);
            float wx = x - fx, wy = y - fy, wz = z - fz;
            float mx = 1.f - wx, my = 1.f - wy, mz = 1.f - wz;
            unsigned ux = (unsigned)fx, uy = (unsigned)fy, uz = (unsigned)fz;
            unsigned hx0 = ux, hx1 = ux + 1u;
            unsigned hy0 = uy * 2654435761u, hy1 = (uy + 1u) * 2654435761u;
            unsigned hz0 = uz * 805459861u,  hz1 = (uz + 1u) * 805459861u;
            float mymz = my * mz, wymz = wy * mz, mywz = my * wz, wywz = wy * wz;
            const float2* tb = stab + (size_t)s * SENT;
            ull f0 = *(const ull*)(tb + (((hx0 ^ hy0 ^ hz0) & SMASK)));
            ull f1 = *(const ull*)(tb + (((hx1 ^ hy0 ^ hz0) & SMASK)));
            ull f2 = *(const ull*)(tb + (((hx0 ^ hy1 ^ hz0) & SMASK)));
            ull f3 = *(const ull*)(tb + (((hx1 ^ hy1 ^ hz0) & SMASK)));
            ull f4 = *(const ull*)(tb + (((hx0 ^ hy0 ^ hz1) & SMASK)));
            ull f5 = *(const ull*)(tb + (((hx1 ^ hy0 ^ hz1) & SMASK)));
            ull f6 = *(const ull*)(tb + (((hx0 ^ hy1 ^ hz1) & SMASK)));
            ull f7 = *(const ull*)(tb + (((hx1 ^ hy1 ^ hz1) & SMASK)));
            ull acc = mul2(f0, splat2(mx * mymz));
            acc = fma2(f1, splat2(wx * mymz), acc);
            acc = fma2(f2, splat2(mx * wymz), acc);
            acc = fma2(f3, splat2(wx * wymz), acc);
            acc = fma2(f4, splat2(mx * mywz), acc);
            acc = fma2(f5, splat2(wx * mywz), acc);
            acc = fma2(f6, splat2(mx * wywz), acc);
            acc = fma2(f7, splat2(wx * wywz), acc);
            a = unpack2(acc);
        } else {
            int l = s - SL;
            float r  = __ldg(&g_res[s]);
            float tx = c.w * r;
            float tf = floorf(tx);
            float tw = tx - tf;
            unsigned t0 = (unsigned)tf;
            const float2* tb = ttab + (size_t)l * TENT;
            ull f0 = *(const ull*)(tb + (t0 & TMASK));
            ull f1 = *(const ull*)(tb + ((t0 + 1u) & TMASK));
            ull acc = mul2(f0, splat2(1.f - tw));
            acc = fma2(f1, splat2(tw), acc);
            a = unpack2(acc);
        }
        u32 hp, lp;
        split2(a.x, a.y, hp, lp);
        int kt = s >> 3, qq = s & 7, reg = qq >> 2, tgq = qq & 3;
        int idx = bidx(kt, lane >> 3, reg, (lane & 7) * 4 + tgq);
        bhi[idx] = hp;
        blo[idx] = lp;
    }
    __syncthreads();

#pragma unroll 1
    for (int layer = 0; layer < 2; layer++) {
        const u32* WH = layer ? g_w2hi : g_w1hi;
        const u32* WL = layer ? g_w2lo : g_w1lo;

        float d[2][4][4];
#pragma unroll
        for (int mt = 0; mt < 2; mt++)
#pragma unroll
            for (int nt = 0; nt < 4; nt++)
#pragma unroll
                for (int e = 0; e < 4; e++) d[mt][nt][e] = 0.f;

#pragma unroll
        for (int kt = 0; kt < 8; kt++) {
            const uint4* pa = (const uint4*)(WH + (size_t)(((w * 8 + kt) * 32 + lane) * 8));
            uint4 A0 = __ldg(pa);
            uint4 A1 = __ldg(pa + 1);
            u32 bh[4][2], bl[4][2];
#pragma unroll
            for (int nt = 0; nt < 4; nt++) {
                bh[nt][0] = bhi[bidx(kt, nt, 0, lane)];
                bh[nt][1] = bhi[bidx(kt, nt, 1, lane)];
                bl[nt][0] = blo[bidx(kt, nt, 0, lane)];
                bl[nt][1] = blo[bidx(kt, nt, 1, lane)];
            }
#pragma unroll
            for (int nt = 0; nt < 4; nt++) {
                mma16816(d[0][nt], A0.x, A0.y, A0.z, A0.w, bh[nt][0], bh[nt][1]);
                mma16816(d[1][nt], A1.x, A1.y, A1.z, A1.w, bh[nt][0], bh[nt][1]);
                mma16816(d[0][nt], A0.x, A0.y, A0.z, A0.w, bl[nt][0], bl[nt][1]);
                mma16816(d[1][nt], A1.x, A1.y, A1.z, A1.w, bl[nt][0], bl[nt][1]);
            }
            const uint4* pl = (const uint4*)(WL + (size_t)(((w * 8 + kt) * 32 + lane) * 8));
            uint4 L0 = __ldg(pl);
            uint4 L1 = __ldg(pl + 1);
#pragma unroll
            for (int nt = 0; nt < 4; nt++) {
                mma16816(d[0][nt], L0.x, L0.y, L0.z, L0.w, bh[nt][0], bh[nt][1]);
                mma16816(d[1][nt], L1.x, L1.y, L1.z, L1.w, bh[nt][0], bh[nt][1]);
            }
        }
        __syncthreads();

        const int g  = lane >> 2;
        const int tg = lane & 3;
        const float* bias = layer ? b2 : b1;
#pragma unroll
        for (int mt = 0; mt < 2; mt++) {
            int j0 = w * 32 + mt * 16 + g;
            float bA = __ldg(bias + j0);
            float bB = __ldg(bias + j0 + 8);
#pragma unroll
            for (int nt = 0; nt < 4; nt++) {
                int p0 = nt * 8 + tg * 2;
                vmat[p0 * VROW + j0]           = fmaxf(d[mt][nt][0] + bA, 0.f);
                vmat[(p0 + 1) * VROW + j0]     = fmaxf(d[mt][nt][1] + bA, 0.f);
                vmat[p0 * VROW + j0 + 8]       = fmaxf(d[mt][nt][2] + bB, 0.f);
                vmat[(p0 + 1) * VROW + j0 + 8] = fmaxf(d[mt][nt][3] + bB, 0.f);
            }
        }
        __syncthreads();

        const int p  = tid >> 2;
        const int q4 = tid & 3;
        float v[32];
        float s1 = 0.f, s2 = 0.f;
        const float4* row = (const float4*)(vmat + p * VROW + q4 * 32);
#pragma unroll
        for (int i8 = 0; i8 < 8; i8++) {
            float4 t = row[i8];
            v[4 * i8] = t.x; v[4 * i8 + 1] = t.y; v[4 * i8 + 2] = t.z; v[4 * i8 + 3] = t.w;
            s1 += (t.x + t.y) + (t.z + t.w);
            s2 += (t.x * t.x + t.y * t.y) + (t.z * t.z + t.w * t.w);
        }
        s1 += __shfl_xor_sync(0xffffffffu, s1, 1);
        s1 += __shfl_xor_sync(0xffffffffu, s1, 2);
        s2 += __shfl_xor_sync(0xffffffffu, s2, 1);
        s2 += __shfl_xor_sync(0xffffffffu, s2, 2);
        float m   = s1 * (1.f / HID);
        float var = s2 * (1.f / HID) - m * m;
        float rs  = rsqrtf(var + 1e-5f);

        const float* gg = (layer ? g2 : g1) + q4 * 32;
        const float* bb = (layer ? bt2 : bt1) + q4 * 32;

        if (layer == 0) {
            __syncthreads();
#pragma unroll
            for (int mm = 0; mm < 16; mm++) {
                float x0 = (v[2 * mm]     - m) * rs * __ldg(gg + 2 * mm)     + __ldg(bb + 2 * mm);
                float x1 = (v[2 * mm + 1] - m) * rs * __ldg(gg + 2 * mm + 1) + __ldg(bb + 2 * mm + 1);
                int kp = q4 * 16 + mm;
                int kt = kp >> 3, qq = kp & 7, reg = qq >> 2, tgq = qq & 3;
                u32 hp, lp;
                split2(x0, x1, hp, lp);
                int idx = bidx(kt, p >> 3, reg, (p & 7) * 4 + tgq);
                bhi[idx] = hp;
                blo[idx] = lp;
            }
            __syncthreads();
        } else {
            float part = 0.f;
#pragma unroll
            for (int i = 0; i < 32; i++) {
                float x = (v[i] - m) * rs * __ldg(gg + i) + __ldg(bb + i);
                part = fmaf(x, __ldg(w3 + q4 * 32 + i), part);
            }
            part += __shfl_xor_sync(0xffffffffu, part, 1);
            part += __shfl_xor_sync(0xffffffffu, part, 2);
            if (q4 == 0) {
                int po = base + p;
                if (po < B) out[po] = part + __ldg(b3);
            }
        }
    }
}

extern "C" void kernel_launch(void* const* d_in, const int* in_sizes, int n_in,
                              void* d_out, int out_size) {
    const float4* coords = (const float4*)d_in[0];
    const float2* stab   = (const float2*)d_in[1];
    const float2* ttab   = (const float2*)d_in[2];
    const float*  w1     = (const float*)d_in[3];
    const float*  b1     = (const float*)d_in[4];
    const float*  g1     = (const float*)d_in[5];
    const float*  be1    = (const float*)d_in[6];
    const float*  w2     = (const float*)d_in[7];
    const float*  b2     = (const float*)d_in[8];
    const float*  g2     = (const float*)d_in[9];
    const float*  be2    = (const float*)d_in[10];
    const float*  w3     = (const float*)d_in[11];
    const float*  b3     = (const float*)d_in[12];
    float* out = (float*)d_out;

    int B = in_sizes[0] / 4;
    if (B > MAXB) B = MAXB;
    int blocks = (B + P - 1) / P;

    setup_kernel<<<128, 256>>>(w1, w2);
    fused_kernel<<<blocks, 128>>>(coords, stab, ttab,
                                  b1, g1, be1, b2, g2, be2, w3, b3, out, B);
}

// round 16
// speedup vs baseline: 1.1470x; 1.0247x over previous
#include <cuda_runtime.h>
#include <cuda_bf16.h>
#include <math.h>

typedef unsigned long long ull;
typedef unsigned int u32;

#define SL 36
#define TL 20
#define SENT (1u << 19)
#define TENT (1u << 17)
#define SMASK (SENT - 1u)
#define TMASK (TENT - 1u)
#define HID 128
#define ENC 112
#define NSLOT (SL + TL)
#define P 32
#define MAXB 131072
#define VROW 132

// weights in DENSE fragment order: [w(4)][kt(8)][mt(2)][lane(32)] x uint4
// (each warp-load of one mt-half is a contiguous 512B span)
__device__ __align__(16) u32 g_w1hi[4 * 8 * 2 * 32 * 4];
__device__ __align__(16) u32 g_w1lo[4 * 8 * 2 * 32 * 4];
__device__ __align__(16) u32 g_w2hi[4 * 8 * 2 * 32 * 4];
__device__ __align__(16) u32 g_w2lo[4 * 8 * 2 * 32 * 4];
__device__ float g_res[NSLOT];

// ---- fp32x2 helpers ---------------------------------------------------------
__device__ __forceinline__ ull splat2(float v) {
    ull r; asm("mov.b64 %0, {%1, %1};" : "=l"(r) : "f"(v)); return r;
}
__device__ __forceinline__ float2 unpack2(ull v) {
    float2 r; asm("mov.b64 {%0, %1}, %2;" : "=f"(r.x), "=f"(r.y) : "l"(v)); return r;
}
__device__ __forceinline__ ull fma2(ull a, ull b, ull c) {
    ull d; asm("fma.rn.f32x2 %0, %1, %2, %3;" : "=l"(d) : "l"(a), "l"(b), "l"(c)); return d;
}
__device__ __forceinline__ ull mul2(ull a, ull b) {
    ull d; asm("mul.rn.f32x2 %0, %1, %2;" : "=l"(d) : "l"(a), "l"(b)); return d;
}

// ---- bf16 split / mma helpers ------------------------------------------------
__device__ __forceinline__ void split2(float x0, float x1, u32& hp, u32& lp) {
    __nv_bfloat16 h0 = __float2bfloat16(x0);
    __nv_bfloat16 h1 = __float2bfloat16(x1);
    __nv_bfloat16 l0 = __float2bfloat16(x0 - __bfloat162float(h0));
    __nv_bfloat16 l1 = __float2bfloat16(x1 - __bfloat162float(h1));
    hp = ((u32)__bfloat16_as_ushort(h1) << 16) | __bfloat16_as_ushort(h0);
    lp = ((u32)__bfloat16_as_ushort(l1) << 16) | __bfloat16_as_ushort(l0);
}

__device__ __forceinline__ void mma16816(float* d, u32 a0, u32 a1, u32 a2, u32 a3,
                                         u32 b0, u32 b1) {
    asm volatile(
        "mma.sync.aligned.m16n8k16.row.col.f32.bf16.bf16.f32 "
        "{%0,%1,%2,%3}, {%4,%5,%6,%7}, {%8,%9}, {%0,%1,%2,%3};"
        : "+f"(d[0]), "+f"(d[1]), "+f"(d[2]), "+f"(d[3])
        : "r"(a0), "r"(a1), "r"(a2), "r"(a3), "r"(b0), "r"(b1));
}

__device__ __forceinline__ int bidx(int kt, int nt, int reg, int lane) {
    return ((kt * 4 + nt) * 2 + reg) * 32 + lane;
}

// ============================================================================
// setup kernel — writes dense fragment layout:
// u32 index = (((w*8+kt)*2 + mt)*32 + lane)*4 + rr
// ============================================================================
__global__ void setup_kernel(const float* __restrict__ w1, const float* __restrict__ w2) {
    int t = blockIdx.x * blockDim.x + threadIdx.x;
    if (blockIdx.x == 0 && threadIdx.x < NSLOT) {
        int s = threadIdx.x;
        double bs = (s < SL) ? (double)1.38f : (double)1.5f;
        int e = (s < SL) ? s : s - SL;
        g_res[s] = floorf(16.0f * (float)pow(bs, (double)e));
    }
    int r     = t & 7;
    int lane  = (t >> 3) & 31;
    int kt    = (t >> 8) & 7;
    int w     = (t >> 11) & 3;
    int half  = (t >> 13) & 1;
    int layer = (t >> 14) & 1;
    int g  = lane >> 2;
    int tg = lane & 3;
    int mt = r >> 2;
    int rr = r & 3;
    int j  = w * 32 + mt * 16 + g + ((rr & 1) ? 8 : 0);
    int k0 = kt * 16 + tg * 2 + ((rr >> 1) ? 8 : 0);
    int k1 = k0 + 1;
    const float* W = layer ? w2 : w1;
    float x0 = (layer || k0 < ENC) ? W[k0 * HID + j] : 0.f;
    float x1 = (layer || k1 < ENC) ? W[k1 * HID + j] : 0.f;
    u32 hp, lp;
    split2(x0, x1, hp, lp);
    int idx = (((w * 8 + kt) * 2 + mt) * 32 + lane) * 4 + rr;
    u32 val = half ? lp : hp;
    if (layer == 0) { if (half) g_w1lo[idx] = val; else g_w1hi[idx] = val; }
    else            { if (half) g_w2lo[idx] = val; else g_w2hi[idx] = val; }
}

// ============================================================================
// Fused kernel: encode (unroll 2) -> bf16 fragments -> 3-term bf16 mma MLP.
// Dense weight loads: each LDG.128 covers a contiguous 512B span.
// ============================================================================
__global__ __launch_bounds__(128, 6)
void fused_kernel(const float4* __restrict__ coords,
                  const float2* __restrict__ stab,
                  const float2* __restrict__ ttab,
                  const float* __restrict__ b1, const float* __restrict__ g1,
                  const float* __restrict__ bt1,
                  const float* __restrict__ b2, const float* __restrict__ g2,
                  const float* __restrict__ bt2,
                  const float* __restrict__ w3, const float* __restrict__ b3,
                  float* __restrict__ out, int B)
{
    __shared__ __align__(16) unsigned char smraw[32 * VROW * 4];
    u32* bhi = (u32*)smraw;
    u32* blo = bhi + 2048;
    float* vmat = (float*)smraw;

    const int tid  = threadIdx.x;
    const int w    = tid >> 5;
    const int lane = tid & 31;
    const int base = blockIdx.x * P;

    bhi[1792 + tid] = 0u; bhi[1920 + tid] = 0u;
    blo[1792 + tid] = 0u; blo[1920 + tid] = 0u;

    int pi = base + lane;
    if (pi >= B) pi = B - 1;
    const float4 c = __ldg(&coords[pi]);

#pragma unroll 2
    for (int i = 0; i < 14; i++) {
        int s = w + 4 * i;
        float2 a;
        if (s < SL) {
            float r = __ldg(&g_res[s]);
            float x = c.x * r, y = c.y * r, z = c.z * r;
            float fx = floorf(x), fy = floorf(y), fz = floorf(z);
            float wx = x - fx, wy = y - fy, wz = z - fz;
            float mx = 1.f - wx, my = 1.f - wy, mz = 1.f - wz;
            unsigned ux = (unsigned)fx, uy = (unsigned)fy, uz = (unsigned)fz;
            unsigned hx0 = ux, hx1 = ux + 1u;
            unsigned hy0 = uy * 2654435761u, hy1 = (uy + 1u) * 2654435761u;
            unsigned hz0 = uz * 805459861u,  hz1 = (uz + 1u) * 805459861u;
            float mymz = my * mz, wymz = wy * mz, mywz = my * wz, wywz = wy * wz;
            const float2* tb = stab + (size_t)s * SENT;
            ull f0 = *(const ull*)(tb + (((hx0 ^ hy0 ^ hz0) & SMASK)));
            ull f1 = *(const ull*)(tb + (((hx1 ^ hy0 ^ hz0) & SMASK)));
            ull f2 = *(const ull*)(tb + (((hx0 ^ hy1 ^ hz0) & SMASK)));
            ull f3 = *(const ull*)(tb + (((hx1 ^ hy1 ^ hz0) & SMASK)));
            ull f4 = *(const ull*)(tb + (((hx0 ^ hy0 ^ hz1) & SMASK)));
            ull f5 = *(const ull*)(tb + (((hx1 ^ hy0 ^ hz1) & SMASK)));
            ull f6 = *(const ull*)(tb + (((hx0 ^ hy1 ^ hz1) & SMASK)));
            ull f7 = *(const ull*)(tb + (((hx1 ^ hy1 ^ hz1) & SMASK)));
            ull acc = mul2(f0, splat2(mx * mymz));
            acc = fma2(f1, splat2(wx * mymz), acc);
            acc = fma2(f2, splat2(mx * wymz), acc);
            acc = fma2(f3, splat2(wx * wymz), acc);
            acc = fma2(f4, splat2(mx * mywz), acc);
            acc = fma2(f5, splat2(wx * mywz), acc);
            acc = fma2(f6, splat2(mx * wywz), acc);
            acc = fma2(f7, splat2(wx * wywz), acc);
            a = unpack2(acc);
        } else {
            int l = s - SL;
            float r  = __ldg(&g_res[s]);
            float tx = c.w * r;
            float tf = floorf(tx);
            float tw = tx - tf;
            unsigned t0 = (unsigned)tf;
            const float2* tb = ttab + (size_t)l * TENT;
            ull f0 = *(const ull*)(tb + (t0 & TMASK));
            ull f1 = *(const ull*)(tb + ((t0 + 1u) & TMASK));
            ull acc = mul2(f0, splat2(1.f - tw));
            acc = fma2(f1, splat2(tw), acc);
            a = unpack2(acc);
        }
        u32 hp, lp;
        split2(a.x, a.y, hp, lp);
        int kt = s >> 3, qq = s & 7, reg = qq >> 2, tgq = qq & 3;
        int idx = bidx(kt, lane >> 3, reg, (lane & 7) * 4 + tgq);
        bhi[idx] = hp;
        blo[idx] = lp;
    }
    __syncthreads();

#pragma unroll 1
    for (int layer = 0; layer < 2; layer++) {
        const u32* WH = layer ? g_w2hi : g_w1hi;
        const u32* WL = layer ? g_w2lo : g_w1lo;

        float d[2][4][4];
#pragma unroll
        for (int mt = 0; mt < 2; mt++)
#pragma unroll
            for (int nt = 0; nt < 4; nt++)
#pragma unroll
                for (int e = 0; e < 4; e++) d[mt][nt][e] = 0.f;

#pragma unroll
        for (int kt = 0; kt < 8; kt++) {
            // dense: A0 span = [(w*8+kt)*2+0][lane], A1 span = [(w*8+kt)*2+1][lane]
            const uint4* ph = (const uint4*)WH + ((w * 8 + kt) * 2) * 32 + lane;
            uint4 A0 = __ldg(ph);
            uint4 A1 = __ldg(ph + 32);
            u32 bh[4][2], bl[4][2];
#pragma unroll
            for (int nt = 0; nt < 4; nt++) {
                bh[nt][0] = bhi[bidx(kt, nt, 0, lane)];
                bh[nt][1] = bhi[bidx(kt, nt, 1, lane)];
                bl[nt][0] = blo[bidx(kt, nt, 0, lane)];
                bl[nt][1] = blo[bidx(kt, nt, 1, lane)];
            }
#pragma unroll
            for (int nt = 0; nt < 4; nt++) {
                mma16816(d[0][nt], A0.x, A0.y, A0.z, A0.w, bh[nt][0], bh[nt][1]);
                mma16816(d[1][nt], A1.x, A1.y, A1.z, A1.w, bh[nt][0], bh[nt][1]);
                mma16816(d[0][nt], A0.x, A0.y, A0.z, A0.w, bl[nt][0], bl[nt][1]);
                mma16816(d[1][nt], A1.x, A1.y, A1.z, A1.w, bl[nt][0], bl[nt][1]);
            }
            const uint4* pl = (const uint4*)WL + ((w * 8 + kt) * 2) * 32 + lane;
            uint4 L0 = __ldg(pl);
            uint4 L1 = __ldg(pl + 32);
#pragma unroll
            for (int nt = 0; nt < 4; nt++) {
                mma16816(d[0][nt], L0.x, L0.y, L0.z, L0.w, bh[nt][0], bh[nt][1]);
                mma16816(d[1][nt], L1.x, L1.y, L1.z, L1.w, bh[nt][0], bh[nt][1]);
            }
        }
        __syncthreads();

        const int g  = lane >> 2;
        const int tg = lane & 3;
        const float* bias = layer ? b2 : b1;
#pragma unroll
        for (int mt = 0; mt < 2; mt++) {
            int j0 = w * 32 + mt * 16 + g;
            float bA = __ldg(bias + j0);
            float bB = __ldg(bias + j0 + 8);
#pragma unroll
            for (int nt = 0; nt < 4; nt++) {
                int p0 = nt * 8 + tg * 2;
                vmat[p0 * VROW + j0]           = fmaxf(d[mt][nt][0] + bA, 0.f);
                vmat[(p0 + 1) * VROW + j0]     = fmaxf(d[mt][nt][1] + bA, 0.f);
                vmat[p0 * VROW + j0 + 8]       = fmaxf(d[mt][nt][2] + bB, 0.f);
                vmat[(p0 + 1) * VROW + j0 + 8] = fmaxf(d[mt][nt][3] + bB, 0.f);
            }
        }
        __syncthreads();

        const int p  = tid >> 2;
        const int q4 = tid & 3;
        float v[32];
        float s1 = 0.f, s2 = 0.f;
        const float4* row = (const float4*)(vmat + p * VROW + q4 * 32);
#pragma unroll
        for (int i8 = 0; i8 < 8; i8++) {
            float4 t = row[i8];
            v[4 * i8] = t.x; v[4 * i8 + 1] = t.y; v[4 * i8 + 2] = t.z; v[4 * i8 + 3] = t.w;
            s1 += (t.x + t.y) + (t.z + t.w);
            s2 += (t.x * t.x + t.y * t.y) + (t.z * t.z + t.w * t.w);
        }
        s1 += __shfl_xor_sync(0xffffffffu, s1, 1);
        s1 += __shfl_xor_sync(0xffffffffu, s1, 2);
        s2 += __shfl_xor_sync(0xffffffffu, s2, 1);
        s2 += __shfl_xor_sync(0xffffffffu, s2, 2);
        float m   = s1 * (1.f / HID);
        float var = s2 * (1.f / HID) - m * m;
        float rs  = rsqrtf(var + 1e-5f);

        const float* gg = (layer ? g2 : g1) + q4 * 32;
        const float* bb = (layer ? bt2 : bt1) + q4 * 32;

        if (layer == 0) {
            __syncthreads();
#pragma unroll
            for (int mm = 0; mm < 16; mm++) {
                float x0 = (v[2 * mm]     - m) * rs * __ldg(gg + 2 * mm)     + __ldg(bb + 2 * mm);
                float x1 = (v[2 * mm + 1] - m) * rs * __ldg(gg + 2 * mm + 1) + __ldg(bb + 2 * mm + 1);
                int kp = q4 * 16 + mm;
                int kt = kp >> 3, qq = kp & 7, reg = qq >> 2, tgq = qq & 3;
                u32 hp, lp;
                split2(x0, x1, hp, lp);
                int idx = bidx(kt, p >> 3, reg, (p & 7) * 4 + tgq);
                bhi[idx] = hp;
                blo[idx] = lp;
            }
            __syncthreads();
        } else {
            float part = 0.f;
#pragma unroll
            for (int i = 0; i < 32; i++) {
                float x = (v[i] - m) * rs * __ldg(gg + i) + __ldg(bb + i);
                part = fmaf(x, __ldg(w3 + q4 * 32 + i), part);
            }
            part += __shfl_xor_sync(0xffffffffu, part, 1);
            part += __shfl_xor_sync(0xffffffffu, part, 2);
            if (q4 == 0) {
                int po = base + p;
                if (po < B) out[po] = part + __ldg(b3);
            }
        }
    }
}

extern "C" void kernel_launch(void* const* d_in, const int* in_sizes, int n_in,
                              void* d_out, int out_size) {
    const float4* coords = (const float4*)d_in[0];
    const float2* stab   = (const float2*)d_in[1];
    const float2* ttab   = (const float2*)d_in[2];
    const float*  w1     = (const float*)d_in[3];
    const float*  b1     = (const float*)d_in[4];
    const float*  g1     = (const float*)d_in[5];
    const float*  be1    = (const float*)d_in[6];
    const float*  w2     = (const float*)d_in[7];
    const float*  b2     = (const float*)d_in[8];
    const float*  g2     = (const float*)d_in[9];
    const float*  be2    = (const float*)d_in[10];
    const float*  w3     = (const float*)d_in[11];
    const float*  b3     = (const float*)d_in[12];
    float* out = (float*)d_out;

    int B = in_sizes[0] / 4;
    if (B > MAXB) B = MAXB;
    int blocks = (B + P - 1) / P;

    setup_kernel<<<128, 256>>>(w1, w2);
    fused_kernel<<<blocks, 128>>>(coords, stab, ttab,
                                  b1, g1, be1, b2, g2, be2, w3, b3, out, B);
}

// round 17
// speedup vs baseline: 1.1483x; 1.0011x over previous
#include <cuda_runtime.h>
#include <cuda_bf16.h>
#include <math.h>

typedef unsigned long long ull;
typedef unsigned int u32;

#define SL 36
#define TL 20
#define SENT (1u << 19)
#define TENT (1u << 17)
#define SMASK (SENT - 1u)
#define TMASK (TENT - 1u)
#define HID 128
#define ENC 112
#define NSLOT (SL + TL)
#define P 32
#define MAXB 131072
#define VROW 132

// weights in DENSE fragment order: [w(4)][kt(8)][mt(2)][lane(32)] x uint4
// (each warp-load of one mt-half is a contiguous 512B span)
__device__ __align__(16) u32 g_w1hi[4 * 8 * 2 * 32 * 4];
__device__ __align__(16) u32 g_w1lo[4 * 8 * 2 * 32 * 4];
__device__ __align__(16) u32 g_w2hi[4 * 8 * 2 * 32 * 4];
__device__ __align__(16) u32 g_w2lo[4 * 8 * 2 * 32 * 4];
__device__ float g_res[NSLOT];

// ---- fp32x2 helpers ---------------------------------------------------------
__device__ __forceinline__ ull splat2(float v) {
    ull r; asm("mov.b64 %0, {%1, %1};" : "=l"(r) : "f"(v)); return r;
}
__device__ __forceinline__ float2 unpack2(ull v) {
    float2 r; asm("mov.b64 {%0, %1}, %2;" : "=f"(r.x), "=f"(r.y) : "l"(v)); return r;
}
__device__ __forceinline__ ull fma2(ull a, ull b, ull c) {
    ull d; asm("fma.rn.f32x2 %0, %1, %2, %3;" : "=l"(d) : "l"(a), "l"(b), "l"(c)); return d;
}
__device__ __forceinline__ ull mul2(ull a, ull b) {
    ull d; asm("mul.rn.f32x2 %0, %1, %2;" : "=l"(d) : "l"(a), "l"(b)); return d;
}

// ---- bf16 split / mma helpers ------------------------------------------------
__device__ __forceinline__ void split2(float x0, float x1, u32& hp, u32& lp) {
    __nv_bfloat16 h0 = __float2bfloat16(x0);
    __nv_bfloat16 h1 = __float2bfloat16(x1);
    __nv_bfloat16 l0 = __float2bfloat16(x0 - __bfloat162float(h0));
    __nv_bfloat16 l1 = __float2bfloat16(x1 - __bfloat162float(h1));
    hp = ((u32)__bfloat16_as_ushort(h1) << 16) | __bfloat16_as_ushort(h0);
    lp = ((u32)__bfloat16_as_ushort(l1) << 16) | __bfloat16_as_ushort(l0);
}

__device__ __forceinline__ void mma16816(float* d, u32 a0, u32 a1, u32 a2, u32 a3,
                                         u32 b0, u32 b1) {
    asm volatile(
        "mma.sync.aligned.m16n8k16.row.col.f32.bf16.bf16.f32 "
        "{%0,%1,%2,%3}, {%4,%5,%6,%7}, {%8,%9}, {%0,%1,%2,%3};"
        : "+f"(d[0]), "+f"(d[1]), "+f"(d[2]), "+f"(d[3])
        : "r"(a0), "r"(a1), "r"(a2), "r"(a3), "r"(b0), "r"(b1));
}

__device__ __forceinline__ int bidx(int kt, int nt, int reg, int lane) {
    return ((kt * 4 + nt) * 2 + reg) * 32 + lane;
}

// ============================================================================
// setup kernel — writes dense fragment layout:
// u32 index = (((w*8+kt)*2 + mt)*32 + lane)*4 + rr
// ============================================================================
__global__ void setup_kernel(const float* __restrict__ w1, const float* __restrict__ w2) {
    int t = blockIdx.x * blockDim.x + threadIdx.x;
    if (blockIdx.x == 0 && threadIdx.x < NSLOT) {
        int s = threadIdx.x;
        double bs = (s < SL) ? (double)1.38f : (double)1.5f;
        int e = (s < SL) ? s : s - SL;
        g_res[s] = floorf(16.0f * (float)pow(bs, (double)e));
    }
    int r     = t & 7;
    int lane  = (t >> 3) & 31;
    int kt    = (t >> 8) & 7;
    int w     = (t >> 11) & 3;
    int half  = (t >> 13) & 1;
    int layer = (t >> 14) & 1;
    int g  = lane >> 2;
    int tg = lane & 3;
    int mt = r >> 2;
    int rr = r & 3;
    int j  = w * 32 + mt * 16 + g + ((rr & 1) ? 8 : 0);
    int k0 = kt * 16 + tg * 2 + ((rr >> 1) ? 8 : 0);
    int k1 = k0 + 1;
    const float* W = layer ? w2 : w1;
    float x0 = (layer || k0 < ENC) ? W[k0 * HID + j] : 0.f;
    float x1 = (layer || k1 < ENC) ? W[k1 * HID + j] : 0.f;
    u32 hp, lp;
    split2(x0, x1, hp, lp);
    int idx = (((w * 8 + kt) * 2 + mt) * 32 + lane) * 4 + rr;
    u32 val = half ? lp : hp;
    if (layer == 0) { if (half) g_w1lo[idx] = val; else g_w1hi[idx] = val; }
    else            { if (half) g_w2lo[idx] = val; else g_w2hi[idx] = val; }
}

// ============================================================================
// Fused kernel: encode (unroll 2) -> bf16 fragments -> 3-term bf16 mma MLP.
// Dense weight loads: each LDG.128 covers a contiguous 512B span.
// ============================================================================
__global__ __launch_bounds__(128, 6)
void fused_kernel(const float4* __restrict__ coords,
                  const float2* __restrict__ stab,
                  const float2* __restrict__ ttab,
                  const float* __restrict__ b1, const float* __restrict__ g1,
                  const float* __restrict__ bt1,
                  const float* __restrict__ b2, const float* __restrict__ g2,
                  const float* __restrict__ bt2,
                  const float* __restrict__ w3, const float* __restrict__ b3,
                  float* __restrict__ out, int B)
{
    __shared__ __align__(16) unsigned char smraw[32 * VROW * 4];
    u32* bhi = (u32*)smraw;
    u32* blo = bhi + 2048;
    float* vmat = (float*)smraw;

    const int tid  = threadIdx.x;
    const int w    = tid >> 5;
    const int lane = tid & 31;
    const int base = blockIdx.x * P;

    bhi[1792 + tid] = 0u; bhi[1920 + tid] = 0u;
    blo[1792 + tid] = 0u; blo[1920 + tid] = 0u;

    int pi = base + lane;
    if (pi >= B) pi = B - 1;
    const float4 c = __ldg(&coords[pi]);

#pragma unroll 2
    for (int i = 0; i < 14; i++) {
        int s = w + 4 * i;
        float2 a;
        if (s < SL) {
            float r = __ldg(&g_res[s]);
            float x = c.x * r, y = c.y * r, z = c.z * r;
            float fx = floorf(x), fy = floorf(y), fz = floorf(z);
            float wx = x - fx, wy = y - fy, wz = z - fz;
            float mx = 1.f - wx, my = 1.f - wy, mz = 1.f - wz;
            unsigned ux = (unsigned)fx, uy = (unsigned)fy, uz = (unsigned)fz;
            unsigned hx0 = ux, hx1 = ux + 1u;
            unsigned hy0 = uy * 2654435761u, hy1 = (uy + 1u) * 2654435761u;
            unsigned hz0 = uz * 805459861u,  hz1 = (uz + 1u) * 805459861u;
            float mymz = my * mz, wymz = wy * mz, mywz = my * wz, wywz = wy * wz;
            const float2* tb = stab + (size_t)s * SENT;
            ull f0 = *(const ull*)(tb + (((hx0 ^ hy0 ^ hz0) & SMASK)));
            ull f1 = *(const ull*)(tb + (((hx1 ^ hy0 ^ hz0) & SMASK)));
            ull f2 = *(const ull*)(tb + (((hx0 ^ hy1 ^ hz0) & SMASK)));
            ull f3 = *(const ull*)(tb + (((hx1 ^ hy1 ^ hz0) & SMASK)));
            ull f4 = *(const ull*)(tb + (((hx0 ^ hy0 ^ hz1) & SMASK)));
            ull f5 = *(const ull*)(tb + (((hx1 ^ hy0 ^ hz1) & SMASK)));
            ull f6 = *(const ull*)(tb + (((hx0 ^ hy1 ^ hz1) & SMASK)));
            ull f7 = *(const ull*)(tb + (((hx1 ^ hy1 ^ hz1) & SMASK)));
            ull acc = mul2(f0, splat2(mx * mymz));
            acc = fma2(f1, splat2(wx * mymz), acc);
            acc = fma2(f2, splat2(mx * wymz), acc);
            acc = fma2(f3, splat2(wx * wymz), acc);
            acc = fma2(f4, splat2(mx * mywz), acc);
            acc = fma2(f5, splat2(wx * mywz), acc);
            acc = fma2(f6, splat2(mx * wywz), acc);
            acc = fma2(f7, splat2(wx * wywz), acc);
            a = unpack2(acc);
        } else {
            int l = s - SL;
            float r  = __ldg(&g_res[s]);
            float tx = c.w * r;
            float tf = floorf(tx);
            float tw = tx - tf;
            unsigned t0 = (unsigned)tf;
            const float2* tb = ttab + (size_t)l * TENT;
            ull f0 = *(const ull*)(tb + (t0 & TMASK));
            ull f1 = *(const ull*)(tb + ((t0 + 1u) & TMASK));
            ull acc = mul2(f0, splat2(1.f - tw));
            acc = fma2(f1, splat2(tw), acc);
            a = unpack2(acc);
        }
        u32 hp, lp;
        split2(a.x, a.y, hp, lp);
        int kt = s >> 3, qq = s & 7, reg = qq >> 2, tgq = qq & 3;
        int idx = bidx(kt, lane >> 3, reg, (lane & 7) * 4 + tgq);
        bhi[idx] = hp;
        blo[idx] = lp;
    }
    __syncthreads();

#pragma unroll 1
    for (int layer = 0; layer < 2; layer++) {
        const u32* WH = layer ? g_w2hi : g_w1hi;
        const u32* WL = layer ? g_w2lo : g_w1lo;

        float d[2][4][4];
#pragma unroll
        for (int mt = 0; mt < 2; mt++)
#pragma unroll
            for (int nt = 0; nt < 4; nt++)
#pragma unroll
                for (int e = 0; e < 4; e++) d[mt][nt][e] = 0.f;

#pragma unroll
        for (int kt = 0; kt < 8; kt++) {
            // dense: A0 span = [(w*8+kt)*2+0][lane], A1 span = [(w*8+kt)*2+1][lane]
            const uint4* ph = (const uint4*)WH + ((w * 8 + kt) * 2) * 32 + lane;
            uint4 A0 = __ldg(ph);
            uint4 A1 = __ldg(ph + 32);
            u32 bh[4][2], bl[4][2];
#pragma unroll
            for (int nt = 0; nt < 4; nt++) {
                bh[nt][0] = bhi[bidx(kt, nt, 0, lane)];
                bh[nt][1] = bhi[bidx(kt, nt, 1, lane)];
                bl[nt][0] = blo[bidx(kt, nt, 0, lane)];
                bl[nt][1] = blo[bidx(kt, nt, 1, lane)];
            }
#pragma unroll
            for (int nt = 0; nt < 4; nt++) {
                mma16816(d[0][nt], A0.x, A0.y, A0.z, A0.w, bh[nt][0], bh[nt][1]);
                mma16816(d[1][nt], A1.x, A1.y, A1.z, A1.w, bh[nt][0], bh[nt][1]);
                mma16816(d[0][nt], A0.x, A0.y, A0.z, A0.w, bl[nt][0], bl[nt][1]);
                mma16816(d[1][nt], A1.x, A1.y, A1.z, A1.w, bl[nt][0], bl[nt][1]);
            }
            const uint4* pl = (const uint4*)WL + ((w * 8 + kt) * 2) * 32 + lane;
            uint4 L0 = __ldg(pl);
            uint4 L1 = __ldg(pl + 32);
#pragma unroll
            for (int nt = 0; nt < 4; nt++) {
                mma16816(d[0][nt], L0.x, L0.y, L0.z, L0.w, bh[nt][0], bh[nt][1]);
                mma16816(d[1][nt], L1.x, L1.y, L1.z, L1.w, bh[nt][0], bh[nt][1]);
            }
        }
        __syncthreads();

        const int g  = lane >> 2;
        const int tg = lane & 3;
        const float* bias = layer ? b2 : b1;
#pragma unroll
        for (int mt = 0; mt < 2; mt++) {
            int j0 = w * 32 + mt * 16 + g;
            float bA = __ldg(bias + j0);
            float bB = __ldg(bias + j0 + 8);
#pragma unroll
            for (int nt = 0; nt < 4; nt++) {
                int p0 = nt * 8 + tg * 2;
                vmat[p0 * VROW + j0]           = fmaxf(d[mt][nt][0] + bA, 0.f);
                vmat[(p0 + 1) * VROW + j0]     = fmaxf(d[mt][nt][1] + bA, 0.f);
                vmat[p0 * VROW + j0 + 8]       = fmaxf(d[mt][nt][2] + bB, 0.f);
                vmat[(p0 + 1) * VROW + j0 + 8] = fmaxf(d[mt][nt][3] + bB, 0.f);
            }
        }
        __syncthreads();

        const int p  = tid >> 2;
        const int q4 = tid & 3;
        float v[32];
        float s1 = 0.f, s2 = 0.f;
        const float4* row = (const float4*)(vmat + p * VROW + q4 * 32);
#pragma unroll
        for (int i8 = 0; i8 < 8; i8++) {
            float4 t = row[i8];
            v[4 * i8] = t.x; v[4 * i8 + 1] = t.y; v[4 * i8 + 2] = t.z; v[4 * i8 + 3] = t.w;
            s1 += (t.x + t.y) + (t.z + t.w);
            s2 += (t.x * t.x + t.y * t.y) + (t.z * t.z + t.w * t.w);
        }
        s1 += __shfl_xor_sync(0xffffffffu, s1, 1);
        s1 += __shfl_xor_sync(0xffffffffu, s1, 2);
        s2 += __shfl_xor_sync(0xffffffffu, s2, 1);
        s2 += __shfl_xor_sync(0xffffffffu, s2, 2);
        float m   = s1 * (1.f / HID);
        float var = s2 * (1.f / HID) - m * m;
        float rs  = rsqrtf(var + 1e-5f);

        const float* gg = (layer ? g2 : g1) + q4 * 32;
        const float* bb = (layer ? bt2 : bt1) + q4 * 32;

        if (layer == 0) {
            __syncthreads();
#pragma unroll
            for (int mm = 0; mm < 16; mm++) {
                float x0 = (v[2 * mm]     - m) * rs * __ldg(gg + 2 * mm)     + __ldg(bb + 2 * mm);
                float x1 = (v[2 * mm + 1] - m) * rs * __ldg(gg + 2 * mm + 1) + __ldg(bb + 2 * mm + 1);
                int kp = q4 * 16 + mm;
                int kt = kp >> 3, qq = kp & 7, reg = qq >> 2, tgq = qq & 3;
                u32 hp, lp;
                split2(x0, x1, hp, lp);
                int idx = bidx(kt, p >> 3, reg, (p & 7) * 4 + tgq);
                bhi[idx] = hp;
                blo[idx] = lp;
            }
            __syncthreads();
        } else {
            float part = 0.f;
#pragma unroll
            for (int i = 0; i < 32; i++) {
                float x = (v[i] - m) * rs * __ldg(gg + i) + __ldg(bb + i);
                part = fmaf(x, __ldg(w3 + q4 * 32 + i), part);
            }
            part += __shfl_xor_sync(0xffffffffu, part, 1);
            part += __shfl_xor_sync(0xffffffffu, part, 2);
            if (q4 == 0) {
                int po = base + p;
                if (po < B) out[po] = part + __ldg(b3);
            }
        }
    }
}

extern "C" void kernel_launch(void* const* d_in, const int* in_sizes, int n_in,
                              void* d_out, int out_size) {
    const float4* coords = (const float4*)d_in[0];
    const float2* stab   = (const float2*)d_in[1];
    const float2* ttab   = (const float2*)d_in[2];
    const float*  w1     = (const float*)d_in[3];
    const float*  b1     = (const float*)d_in[4];
    const float*  g1     = (const float*)d_in[5];
    const float*  be1    = (const float*)d_in[6];
    const float*  w2     = (const float*)d_in[7];
    const float*  b2     = (const float*)d_in[8];
    const float*  g2     = (const float*)d_in[9];
    const float*  be2    = (const float*)d_in[10];
    const float*  w3     = (const float*)d_in[11];
    const float*  b3     = (const float*)d_in[12];
    float* out = (float*)d_out;

    int B = in_sizes[0] / 4;
    if (B > MAXB) B = MAXB;
    int blocks = (B + P - 1) / P;

    setup_kernel<<<128, 256>>>(w1, w2);
    fused_kernel<<<blocks, 128>>>(coords, stab, ttab,
                                  b1, g1, be1, b2, g2, be2, w3, b3, out, B);
}